// round 8
// baseline (speedup 1.0000x reference)
#include <cuda_runtime.h>
#include <cstdint>

using u64 = unsigned long long;

// Problem constants
constexpr int B_ = 16, C_ = 128, H_ = 72, W_ = 200, K_ = 9;
constexpr int CS = H_ * W_;
constexpr size_t BS = (size_t)C_ * CS;
constexpr size_t TOTAL = (size_t)B_ * BS;
constexpr int NCIP = C_ / 2;             // 64 ci-pairs
constexpr int NR = NCIP * K_;            // 576 weight rows (r = cip*9+k)
constexpr int TCO = 16;                  // c_out per CTA
constexpr int NCOG = TCO / 2;            // 8 co-pairs per CTA

// Scratch: transposed layout + re-laid-out weights (4 directions)
// g_wp2[dir][r][cg][p]: u64 = pack2(w[2cg+p][2cip][k], w[2cg+p][2cip+1][k]),
// cg = global co-pair (0..63). 16B chunk (p=0,1) is cp.async-able.
__device__ float g_tbuf[TOTAL];
__device__ __align__(16) u64 g_wp2[4 * NR * 64 * 2];

__device__ __forceinline__ void fma2(u64& d, u64 a, u64 b) {
    asm("fma.rn.f32x2 %0, %1, %2, %0;" : "+l"(d) : "l"(a), "l"(b));
}
__device__ __forceinline__ u64 pack2(float a, float b) {
    u64 r; asm("mov.b64 %0, {%1, %2};" : "=l"(r) : "f"(a), "f"(b)); return r;
}
__device__ __forceinline__ float hsum2(u64 v) {
    float x, y; asm("mov.b64 {%0, %1}, %2;" : "=f"(x), "=f"(y) : "l"(v));
    return x + y;
}
__device__ __forceinline__ void cp_async16(uint32_t saddr, const void* g) {
    asm volatile("cp.async.cg.shared.global [%0], [%1], 16;" :: "r"(saddr), "l"(g));
}
__device__ __forceinline__ void cp_async_wait_all() {
    asm volatile("cp.async.commit_group;\n\tcp.async.wait_group 0;" ::: "memory");
}

__global__ void prep_weights(const float* w0, const float* w1,
                             const float* w2, const float* w3) {
    const float* ws[4] = {w0, w1, w2, w3};
    const int tot = NR * 64 * 2;
    for (int i = blockIdx.x * blockDim.x + threadIdx.x; i < 4 * tot;
         i += gridDim.x * blockDim.x) {
        int d = i / tot, rem = i % tot;
        int r = rem / 128, e = rem % 128;
        int cg = e / 2, p = e % 2;
        int co = 2 * cg + p;
        int cip = r / K_, k = r % K_;
        const float* w = ws[d];
        g_wp2[i] = pack2(w[(size_t)co * C_ * K_ + (2 * cip) * K_ + k],
                         w[(size_t)co * C_ * K_ + (2 * cip + 1) * K_ + k]);
    }
}

// One scan step: cur[b,co,j] += relu( sum_{ci,k} w[co,ci,k] * prev[b,ci,j+k-4] )
// Thread map t = jg*8 + cog: cog fastest -> all smem loads conflict-free (N=1).
// Each thread: 2 c_out (co pair) x JT j positions. fma2 pairs over (even ci, odd ci).
template <int L, int JT, int NT>
__global__ void __launch_bounds__(NT, 1)
step_kernel(float* __restrict__ base, const u64* __restrict__ wp2,
            int prevIdx, int curIdx) {
    constexpr int PSTRF = L + 8;                 // f32 plane row stride (16B mult)
    constexpr int CH = L / 4;                    // 16B chunks per row
    extern __shared__ __align__(16) float smf[];
    // layout: w2_s [NR][8 cog][2] u64 = NR*128B, then plane0 [64][PSTRF], plane1
    u64*   w2_s = (u64*)smf;
    float* p0   = smf + NR * 32;                 // NR*16 u64 = NR*32 floats
    float* p1   = p0 + NCIP * PSTRF;

    const int t = threadIdx.x;
    const int cobase = blockIdx.y * TCO;
    const int b = blockIdx.z;
    float* __restrict__ bb = base + (size_t)b * BS;
    const float* __restrict__ prow = bb + (size_t)prevIdx * L;
    float* __restrict__ crow = bb + (size_t)curIdx * L;

    const int cog = t & 7;
    const int jg = t >> 3;
    const int j0 = jg * JT;
    const int co0 = cobase + 2 * cog;            // this thread's first c_out

    // ---- stage weights: NR*8 chunks of 16B, dst linear ----
    {
        const uint32_t wb = (uint32_t)__cvta_generic_to_shared(w2_s);
        const int cg0 = cobase / 2;
        #pragma unroll
        for (int i = t; i < NR * 8; i += NT) {
            int r = i >> 3, cg = i & 7;
            cp_async16(wb + (uint32_t)i * 16u,
                       wp2 + ((size_t)r * 64 + cg0 + cg) * 2);
        }
    }
    // ---- stage prev row planes (even/odd ci), contiguous 16B chunks ----
    {
        const uint32_t pb0 = (uint32_t)__cvta_generic_to_shared(p0);
        const uint32_t pb1 = (uint32_t)__cvta_generic_to_shared(p1);
        #pragma unroll
        for (int i = t; i < NCIP * 2 * CH; i += NT) {
            int c = i % CH, e = i / CH;
            int p = e & 1, cip = e >> 1;
            uint32_t dst = (p ? pb1 : pb0) + (uint32_t)(cip * PSTRF + 4 + c * 4) * 4u;
            cp_async16(dst, prow + (size_t)(2 * cip + p) * CS + c * 4);
        }
    }
    // ---- zero plane halos (8 f32 per row per plane) ----
    for (int i = t; i < NCIP * 2; i += NT) {
        float* pl = (i & 1) ? p1 : p0;
        int row = i >> 1;
        #pragma unroll
        for (int q = 0; q < 4; ++q) {
            pl[row * PSTRF + q] = 0.f;
            pl[row * PSTRF + 4 + L + q] = 0.f;
        }
    }
    // ---- prefetch cur-row base values (hide under cp.async) ----
    float xv0[JT], xv1[JT];
    #pragma unroll
    for (int n = 0; n < JT; ++n) {
        xv0[n] = crow[(size_t)co0 * CS + j0 + n];
        xv1[n] = crow[(size_t)(co0 + 1) * CS + j0 + n];
    }

    cp_async_wait_all();
    __syncthreads();

    u64 acc0[JT], acc1[JT];
    #pragma unroll
    for (int n = 0; n < JT; ++n) { acc0[n] = 0ull; acc1[n] = 0ull; }

    const float* r0 = p0 + j0;
    const float* r1 = p1 + j0;
    const u64* wr = w2_s + cog * 2;

    #pragma unroll 2
    for (int cip = 0; cip < NCIP; ++cip) {
        // paired window: (even-ci val, odd-ci val) per tap
        u64 wpair[JT + 8];
        #pragma unroll
        for (int q = 0; q < JT + 8; ++q) wpair[q] = pack2(r0[q], r1[q]);
        #pragma unroll
        for (int k = 0; k < K_; ++k) {
            // LDS.128: weights for both c_outs at (cip,k)
            const u64 wa = wr[(size_t)(cip * K_ + k) * 16 + 0];
            const u64 wb = wr[(size_t)(cip * K_ + k) * 16 + 1];
            #pragma unroll
            for (int n = 0; n < JT; ++n) {
                fma2(acc0[n], wa, wpair[k + n]);
                fma2(acc1[n], wb, wpair[k + n]);
            }
        }
        r0 += PSTRF; r1 += PSTRF;
    }

    #pragma unroll
    for (int n = 0; n < JT; ++n) {
        crow[(size_t)co0 * CS + j0 + n]       = xv0[n] + fmaxf(hsum2(acc0[n]), 0.f);
        crow[(size_t)(co0 + 1) * CS + j0 + n] = xv1[n] + fmaxf(hsum2(acc1[n]), 0.f);
    }
}

// Transpose per (b,c) slab: src slab R x Cc (row-major) -> dst slab Cc x R.
__global__ void transpose_kernel(const float* __restrict__ src, float* __restrict__ dst,
                                 int R, int Cc) {
    __shared__ float tile[32][33];
    const size_t slab = blockIdx.z;
    const float* s = src + slab * (size_t)(R * Cc);
    float* d = dst + slab * (size_t)(R * Cc);
    const int c0 = blockIdx.x * 32;
    const int r0 = blockIdx.y * 32;

    #pragma unroll
    for (int i = 0; i < 32; i += 8) {
        int r = r0 + threadIdx.y + i, c = c0 + threadIdx.x;
        if (r < R && c < Cc) tile[threadIdx.y + i][threadIdx.x] = s[(size_t)r * Cc + c];
    }
    __syncthreads();
    #pragma unroll
    for (int i = 0; i < 32; i += 8) {
        int c = c0 + threadIdx.y + i, r = r0 + threadIdx.x;
        if (r < R && c < Cc) d[(size_t)c * R + r] = tile[threadIdx.x][threadIdx.y + i];
    }
}

// W pass: JT=5, NT=320 (40 jg x 8 cog); H pass: JT=3, NT=192 (24 jg x 8 cog)
constexpr int SMEM_W = NR * 128 + 2 * NCIP * (W_ + 8) * 4;  // 73,728 + 106,496
constexpr int SMEM_H = NR * 128 + 2 * NCIP * (H_ + 8) * 4;  // 73,728 + 40,960
static_assert(SMEM_W <= 227 * 1024, "smem W over limit");
static_assert(SMEM_H <= 227 * 1024, "smem H over limit");

extern "C" void kernel_launch(void* const* d_in, const int* in_sizes, int n_in,
                              void* d_out, int out_size) {
    const float* x  = (const float*)d_in[0];
    const float* wd = (const float*)d_in[1];
    const float* wu = (const float*)d_in[2];
    const float* wr = (const float*)d_in[3];
    const float* wl = (const float*)d_in[4];
    float* out = (float*)d_out;

    // one-time setup on the (uncaptured) correctness call only
    static float* tbuf = nullptr;
    static u64* wp = nullptr;
    static bool init_done = false;
    if (!init_done) {
        cudaGetSymbolAddress((void**)&tbuf, g_tbuf);
        cudaGetSymbolAddress((void**)&wp, g_wp2);
        cudaFuncSetAttribute((const void*)step_kernel<W_, 5, 320>,
                             cudaFuncAttributeMaxDynamicSharedMemorySize, SMEM_W);
        cudaFuncSetAttribute((const void*)step_kernel<H_, 3, 192>,
                             cudaFuncAttributeMaxDynamicSharedMemorySize, SMEM_H);
        init_done = true;
    }

    // re-lay-out weights (reads inputs every call -> deterministic)
    prep_weights<<<256, 256>>>(wd, wu, wr, wl);

    // working copy of x (scan runs in-place on out)
    cudaMemcpyAsync(out, x, TOTAL * sizeof(float), cudaMemcpyDeviceToDevice);

    const size_t DSTR = (size_t)NR * 64 * 2;
    const u64* wpd = wp + 0 * DSTR;
    const u64* wpu = wp + 1 * DSTR;
    const u64* wpr = wp + 2 * DSTR;
    const u64* wpl = wp + 3 * DSTR;

    // ---- down / up: conv along W (contiguous), scan over H ----
    const dim3 gw(1, 8, 16);
    for (int h = 1; h < H_; ++h)
        step_kernel<W_, 5, 320><<<gw, 320, SMEM_W>>>(out, wpd, h - 1, h);
    for (int h = H_ - 2; h >= 0; --h)
        step_kernel<W_, 5, 320><<<gw, 320, SMEM_W>>>(out, wpu, h + 1, h);

    // ---- transpose (B,C,H,W) -> (B,C,W,H) ----
    const dim3 tb(32, 8);
    const dim3 tg1((W_ + 31) / 32, (H_ + 31) / 32, B_ * C_);
    transpose_kernel<<<tg1, tb>>>(out, tbuf, H_, W_);

    // ---- right / left: conv along H (now contiguous), scan over W ----
    const dim3 gh(1, 8, 16);
    for (int w = 1; w < W_; ++w)
        step_kernel<H_, 3, 192><<<gh, 192, SMEM_H>>>(tbuf, wpr, w - 1, w);
    for (int w = W_ - 2; w >= 0; --w)
        step_kernel<H_, 3, 192><<<gh, 192, SMEM_H>>>(tbuf, wpl, w + 1, w);

    // ---- transpose back ----
    const dim3 tg2((H_ + 31) / 32, (W_ + 31) / 32, B_ * C_);
    transpose_kernel<<<tg2, tb>>>(tbuf, out, W_, H_);
}